// round 6
// baseline (speedup 1.0000x reference)
#include <cuda_runtime.h>
#include <cuda_bf16.h>
#include <cstdint>

#define BATCH 8192
#define MDIM  512
#define NDIM  2048

typedef __nv_bfloat16 bf16;

// ---------------- static device scratch (no allocs allowed) ----------------
__device__ __align__(256) bf16 g_xh[(size_t)BATCH * NDIM];
__device__ __align__(256) bf16 g_xl[(size_t)BATCH * NDIM];
__device__ __align__(256) bf16 g_rh[(size_t)BATCH * MDIM];
__device__ __align__(256) bf16 g_rl[(size_t)BATCH * MDIM];
__device__ __align__(256) bf16 g_yh[(size_t)BATCH * MDIM];
__device__ __align__(256) bf16 g_yl[(size_t)BATCH * MDIM];
__device__ __align__(256) bf16 g_Ah[(size_t)MDIM * NDIM];
__device__ __align__(256) bf16 g_Al[(size_t)MDIM * NDIM];
__device__ __align__(256) bf16 g_Wh[(size_t)NDIM * MDIM];
__device__ __align__(256) bf16 g_Wl[(size_t)NDIM * MDIM];

// ---------------- PTX helpers (base-ISA only) ----------------
__device__ __forceinline__ uint32_t smem_u32(const void* p) {
    uint32_t a;
    asm("{ .reg .u64 t; cvta.to.shared.u64 t, %1; cvt.u32.u64 %0, t; }" : "=r"(a) : "l"(p));
    return a;
}
__device__ __forceinline__ void cpa16(uint32_t dst, const void* src) {
    asm volatile("cp.async.cg.shared.global [%0], [%1], 16;" :: "r"(dst), "l"(src));
}
__device__ __forceinline__ void cpa_commit() { asm volatile("cp.async.commit_group;" ::: "memory"); }
template<int N> __device__ __forceinline__ void cpa_wait() {
    asm volatile("cp.async.wait_group %0;" :: "n"(N) : "memory");
}
__device__ __forceinline__ void ldm_x4(uint32_t* r, uint32_t addr) {
    asm volatile("ldmatrix.sync.aligned.m8n8.x4.shared.b16 {%0,%1,%2,%3}, [%4];"
        : "=r"(r[0]), "=r"(r[1]), "=r"(r[2]), "=r"(r[3]) : "r"(addr));
}
__device__ __forceinline__ void mma_bf16(float* d, const uint32_t* a, const uint32_t* b) {
    asm volatile("mma.sync.aligned.m16n8k16.row.col.f32.bf16.bf16.f32 "
        "{%0,%1,%2,%3}, {%4,%5,%6,%7}, {%8,%9}, {%0,%1,%2,%3};"
        : "+f"(d[0]), "+f"(d[1]), "+f"(d[2]), "+f"(d[3])
        : "r"(a[0]), "r"(a[1]), "r"(a[2]), "r"(a[3]), "r"(b[0]), "r"(b[1]));
}

// ---------------- fp32 -> bf16 hi/lo split ----------------
__global__ void split_kernel(const float* __restrict__ s, bf16* __restrict__ h,
                             bf16* __restrict__ l, int n4) {
    int i = blockIdx.x * 256 + threadIdx.x;
    if (i >= n4) return;
    float4 v = reinterpret_cast<const float4*>(s)[i];
    bf16 h0 = __float2bfloat16(v.x), h1 = __float2bfloat16(v.y);
    bf16 h2 = __float2bfloat16(v.z), h3 = __float2bfloat16(v.w);
    __nv_bfloat162 hp0{h0, h1}, hp1{h2, h3};
    __nv_bfloat162 lp0{__float2bfloat16(v.x - __bfloat162float(h0)),
                       __float2bfloat16(v.y - __bfloat162float(h1))};
    __nv_bfloat162 lp1{__float2bfloat16(v.z - __bfloat162float(h2)),
                       __float2bfloat16(v.w - __bfloat162float(h3))};
    reinterpret_cast<__nv_bfloat162*>(h)[i * 2 + 0] = hp0;
    reinterpret_cast<__nv_bfloat162*>(h)[i * 2 + 1] = hp1;
    reinterpret_cast<__nv_bfloat162*>(l)[i * 2 + 0] = lp0;
    reinterpret_cast<__nv_bfloat162*>(l)[i * 2 + 1] = lp1;
}

// ---------------- HMMA split-bf16 GEMM: 4-stage KC=16, single sync ----------------
// C[b,p] = sum_k X[b,k]*Wm[p,k]  (both K-major). 3-product split: hh + hl + lh.
// MODE 0: f = mu*acc         -> outf + splits
// MODE 1: f = acc - aux      -> splits only
// MODE 2: f = aux - mu*acc   -> outf only
#define PITCH 48                       // 16 bf16 (32B) + 16B pad; r*48 mod 128 -> 8 distinct slots
#define TILE_B (128 * PITCH)           // 6144 B per tile
#define STAGE_B (4 * TILE_B)           // Xh, Xl, Wh, Wl = 24576 B
#define NSTAGE 4
#define SMEM_B (NSTAGE * STAGE_B)      // 98304 B -> two CTAs per SM

template<int MODE>
__global__ __launch_bounds__(256, 2)
void mma_gemm(const bf16* __restrict__ Xh, const bf16* __restrict__ Xl,
              const bf16* __restrict__ Bh, const bf16* __restrict__ Bl,
              int K, int P,
              float* __restrict__ outf, bf16* __restrict__ outh, bf16* __restrict__ outl,
              const float* __restrict__ aux, const float* __restrict__ mu, int muidx)
{
    extern __shared__ char smem[];
    const uint32_t sb = smem_u32(smem);
    const int tid = threadIdx.x, lane = tid & 31, wid = tid >> 5;
    const int wr = wid >> 2, wc = wid & 3;          // 2x4 warp grid, warp tile 64x32
    const int b0 = blockIdx.x * 128, p0 = blockIdx.y * 128;

    float acc[4][4][4];
    #pragma unroll
    for (int i = 0; i < 4; i++)
        #pragma unroll
        for (int j = 0; j < 4; j++)
            #pragma unroll
            for (int q = 0; q < 4; q++) acc[i][j][q] = 0.f;

    const int nch = K >> 4;   // KC = 16

    auto load_stage = [&](int s, int c) {
        const int k0 = c * 16;
        const uint32_t st = sb + s * STAGE_B;
        const bf16* srcs[4] = { Xh + (size_t)b0 * K + k0, Xl + (size_t)b0 * K + k0,
                                Bh + (size_t)p0 * K + k0, Bl + (size_t)p0 * K + k0 };
        const int row = tid >> 1, ch = tid & 1;      // 256 threads -> 128 rows x 2 chunks
        #pragma unroll
        for (int t = 0; t < 4; t++)
            cpa16(st + t * TILE_B + row * PITCH + ch * 16,
                  srcs[t] + (size_t)row * K + ch * 8);
        cpa_commit();
    };

    load_stage(0, 0);
    load_stage(1, 1);
    load_stage(2, 2);

    for (int c = 0; c < nch; c++) {
        const int s = c & (NSTAGE - 1);
        cpa_wait<2>();
        __syncthreads();
        // prefetch BEFORE compute; target stage (c+3)&3 is not in use
        if (c + 3 < nch) load_stage((c + 3) & (NSTAGE - 1), c + 3);
        else cpa_commit();               // empty group keeps wait<2> accounting uniform

        const uint32_t xs = sb + s * STAGE_B;
        const uint32_t ws = xs + 2 * TILE_B;

        uint32_t ah[4][4], al[4][4];
        #pragma unroll
        for (int mi = 0; mi < 4; mi++) {
            uint32_t a = xs + (uint32_t)(wr * 64 + mi * 16 + (lane & 15)) * PITCH
                       + ((lane >> 4) << 4);
            ldm_x4(ah[mi], a);
            ldm_x4(al[mi], a + TILE_B);
        }
        #pragma unroll
        for (int nb = 0; nb < 2; nb++) {
            uint32_t a = ws + (uint32_t)(wc * 32 + nb * 16 + ((lane >> 4) << 3)
                       + (lane & 7)) * PITCH
                       + (((lane >> 3) & 1) << 4);
            uint32_t bh[4], bl[4];
            ldm_x4(bh, a);
            ldm_x4(bl, a + TILE_B);
            #pragma unroll
            for (int mi = 0; mi < 4; mi++) {
                mma_bf16(acc[mi][nb*2],   ah[mi], bh);
                mma_bf16(acc[mi][nb*2+1], ah[mi], bh + 2);
            }
            #pragma unroll
            for (int mi = 0; mi < 4; mi++) {
                mma_bf16(acc[mi][nb*2],   ah[mi], bl);
                mma_bf16(acc[mi][nb*2+1], ah[mi], bl + 2);
            }
            #pragma unroll
            for (int mi = 0; mi < 4; mi++) {
                mma_bf16(acc[mi][nb*2],   al[mi], bh);
                mma_bf16(acc[mi][nb*2+1], al[mi], bh + 2);
            }
        }
    }

    // ---------------- epilogue ----------------
    const float m = (MODE != 1) ? __ldg(mu + muidx) : 0.f;
    const int rbase = b0 + wr * 64 + (lane >> 2);
    const int cbase = p0 + wc * 32 + (lane & 3) * 2;

    #pragma unroll
    for (int mi = 0; mi < 4; mi++) {
        #pragma unroll
        for (int h = 0; h < 2; h++) {
            const int row = rbase + mi * 16 + h * 8;
            #pragma unroll
            for (int ni = 0; ni < 4; ni++) {
                const size_t off = (size_t)row * P + cbase + ni * 8;
                float v0 = acc[mi][ni][h * 2], v1 = acc[mi][ni][h * 2 + 1];
                if (MODE == 0) { v0 *= m; v1 *= m; }
                else {
                    float2 a2 = *reinterpret_cast<const float2*>(aux + off);
                    if (MODE == 1) { v0 -= a2.x; v1 -= a2.y; }
                    else { v0 = a2.x - m * v0; v1 = a2.y - m * v1; }
                }
                if (MODE == 0 || MODE == 2)
                    *reinterpret_cast<float2*>(outf + off) = make_float2(v0, v1);
                if (MODE == 0 || MODE == 1) {
                    bf16 h0 = __float2bfloat16(v0), h1 = __float2bfloat16(v1);
                    __nv_bfloat162 hp{h0, h1};
                    __nv_bfloat162 lp{__float2bfloat16(v0 - __bfloat162float(h0)),
                                      __float2bfloat16(v1 - __bfloat162float(h1))};
                    *reinterpret_cast<__nv_bfloat162*>(outh + off) = hp;
                    *reinterpret_cast<__nv_bfloat162*>(outl + off) = lp;
                }
            }
        }
    }
}

// ---------------- shrink: exact kth-largest via bitwise binary search ----------------
__global__ __launch_bounds__(256, 4)
void shrink2(float* __restrict__ x, bf16* __restrict__ xh, bf16* __restrict__ xl,
             const float* __restrict__ beta, int bidx, int kth)
{
    __shared__ int wsum[2][8];
    const int tid = threadIdx.x, wid = tid >> 5, lane = tid & 31;
    float* row = x + (size_t)blockIdx.x * NDIM;
    const int e0 = tid * 8;

    float e[8];
    float4 a = *reinterpret_cast<const float4*>(row + e0);
    float4 b4 = *reinterpret_cast<const float4*>(row + e0 + 4);
    e[0]=a.x; e[1]=a.y; e[2]=a.z; e[3]=a.w; e[4]=b4.x; e[5]=b4.y; e[6]=b4.z; e[7]=b4.w;
    uint32_t k[8];
    #pragma unroll
    for (int i = 0; i < 8; i++) k[i] = __float_as_uint(fabsf(e[i]));

    uint32_t thr = 0;
    for (int bit = 30; bit >= 0; bit--) {
        uint32_t cand = thr | (1u << bit);
        int c = 0;
        #pragma unroll
        for (int i = 0; i < 8; i++) c += (k[i] >= cand);
        c = __reduce_add_sync(0xFFFFFFFFu, c);
        const int buf = bit & 1;
        if (lane == 0) wsum[buf][wid] = c;
        __syncthreads();
        int tot = wsum[buf][0]+wsum[buf][1]+wsum[buf][2]+wsum[buf][3]
                + wsum[buf][4]+wsum[buf][5]+wsum[buf][6]+wsum[buf][7];
        if (tot >= kth) thr = cand;
    }

    const float thf = __uint_as_float(thr);
    const float b = beta[bidx];
    float r[8];
    #pragma unroll
    for (int i = 0; i < 8; i++) {
        float val = e[i];
        float u = val / b;
        float soft = b * copysignf(fmaxf(fabsf(u) - 1.0f, 0.0f), u);
        r[i] = (fabsf(val) >= thf) ? val : soft;
    }
    *reinterpret_cast<float4*>(row + e0)     = make_float4(r[0], r[1], r[2], r[3]);
    *reinterpret_cast<float4*>(row + e0 + 4) = make_float4(r[4], r[5], r[6], r[7]);

    const size_t go = (size_t)blockIdx.x * NDIM + e0;
    #pragma unroll
    for (int i = 0; i < 8; i += 2) {
        bf16 h0 = __float2bfloat16(r[i]), h1 = __float2bfloat16(r[i+1]);
        __nv_bfloat162 hp{h0, h1};
        __nv_bfloat162 lp{__float2bfloat16(r[i]   - __bfloat162float(h0)),
                          __float2bfloat16(r[i+1] - __bfloat162float(h1))};
        *reinterpret_cast<__nv_bfloat162*>(xh + go + i) = hp;
        *reinterpret_cast<__nv_bfloat162*>(xl + go + i) = lp;
    }
}

// ---------------------------------------------------------------------------
extern "C" void kernel_launch(void* const* d_in, const int* in_sizes, int n_in,
                              void* d_out, int out_size)
{
    const float* y    = (const float*)d_in[0];   // [8192, 512]
    const float* A    = (const float*)d_in[1];   // [512, 2048]
    const float* W    = (const float*)d_in[2];   // [2048, 512] = A^T
    const float* beta = (const float*)d_in[3];
    const float* mu   = (const float*)d_in[4];
    float* x = (float*)d_out;                    // [8192, 2048]

    cudaFuncSetAttribute(mma_gemm<0>, cudaFuncAttributeMaxDynamicSharedMemorySize, SMEM_B);
    cudaFuncSetAttribute(mma_gemm<1>, cudaFuncAttributeMaxDynamicSharedMemorySize, SMEM_B);
    cudaFuncSetAttribute(mma_gemm<2>, cudaFuncAttributeMaxDynamicSharedMemorySize, SMEM_B);

    bf16 *xh, *xl, *rh, *rl, *yh, *yl, *Ahp, *Alp, *Wh, *Wl;
    { void* p; cudaGetSymbolAddress(&p, g_xh); xh = (bf16*)p; }
    { void* p; cudaGetSymbolAddress(&p, g_xl); xl = (bf16*)p; }
    { void* p; cudaGetSymbolAddress(&p, g_rh); rh = (bf16*)p; }
    { void* p; cudaGetSymbolAddress(&p, g_rl); rl = (bf16*)p; }
    { void* p; cudaGetSymbolAddress(&p, g_yh); yh = (bf16*)p; }
    { void* p; cudaGetSymbolAddress(&p, g_yl); yl = (bf16*)p; }
    { void* p; cudaGetSymbolAddress(&p, g_Ah); Ahp = (bf16*)p; }
    { void* p; cudaGetSymbolAddress(&p, g_Al); Alp = (bf16*)p; }
    { void* p; cudaGetSymbolAddress(&p, g_Wh); Wh = (bf16*)p; }
    { void* p; cudaGetSymbolAddress(&p, g_Wl); Wl = (bf16*)p; }

    // splits of inputs
    {
        int n4 = BATCH * MDIM / 4;
        split_kernel<<<(n4 + 255) / 256, 256>>>(y, yh, yl, n4);
        n4 = MDIM * NDIM / 4;
        split_kernel<<<(n4 + 255) / 256, 256>>>(A, Ahp, Alp, n4);
        split_kernel<<<(n4 + 255) / 256, 256>>>(W, Wh, Wl, n4);
    }

    const dim3 blk(256);
    const dim3 gN(BATCH / 128, NDIM / 128);   // (64, 16)
    const dim3 gM(BATCH / 128, MDIM / 128);   // (64, 4)
    const int kth[6] = {0, 24, 49, 73, 98, 122};

    // x0 = mu0 * (y @ A):  X = y (K=512), B = W rows ([N,K]), P=2048
    mma_gemm<0><<<gN, blk, SMEM_B>>>(yh, yl, Wh, Wl, MDIM, NDIM,
                                     x, xh, xl, nullptr, mu, 0);

    for (int t = 1; t <= 5; t++) {
        // r = x @ A.T - y:  X = x (K=2048), B = A rows, P=512
        mma_gemm<1><<<gM, blk, SMEM_B>>>(xh, xl, Ahp, Alp, NDIM, MDIM,
                                         nullptr, rh, rl, y, mu, t);
        // v = x - mu*(r @ W.T):  X = r (K=512), B = W rows, P=2048 (in-place on x)
        mma_gemm<2><<<gN, blk, SMEM_B>>>(rh, rl, Wh, Wl, MDIM, NDIM,
                                         x, nullptr, nullptr, x, mu, t);
        // x = shrink(v)
        shrink2<<<BATCH, blk>>>(x, xh, xl, beta, t, kth[t]);
    }
}

// round 8
// speedup vs baseline: 1.0230x; 1.0230x over previous
#include <cuda_runtime.h>
#include <cuda_bf16.h>
#include <cstdint>

#define BATCH 8192
#define MDIM  512
#define NDIM  2048

typedef __nv_bfloat16 bf16;

// ---------------- static device scratch (no allocs allowed) ----------------
__device__ __align__(256) bf16 g_xh[(size_t)BATCH * NDIM];
__device__ __align__(256) bf16 g_xl[(size_t)BATCH * NDIM];
__device__ __align__(256) bf16 g_rh[(size_t)BATCH * MDIM];
__device__ __align__(256) bf16 g_rl[(size_t)BATCH * MDIM];
__device__ __align__(256) bf16 g_yh[(size_t)BATCH * MDIM];
__device__ __align__(256) bf16 g_yl[(size_t)BATCH * MDIM];
__device__ __align__(256) bf16 g_Ah[(size_t)MDIM * NDIM];
__device__ __align__(256) bf16 g_Al[(size_t)MDIM * NDIM];
__device__ __align__(256) bf16 g_Wh[(size_t)NDIM * MDIM];
__device__ __align__(256) bf16 g_Wl[(size_t)NDIM * MDIM];

// ---------------- PTX helpers (base-ISA only) ----------------
__device__ __forceinline__ uint32_t smem_u32(const void* p) {
    uint32_t a;
    asm("{ .reg .u64 t; cvta.to.shared.u64 t, %1; cvt.u32.u64 %0, t; }" : "=r"(a) : "l"(p));
    return a;
}
__device__ __forceinline__ void cpa16(uint32_t dst, const void* src) {
    asm volatile("cp.async.cg.shared.global [%0], [%1], 16;" :: "r"(dst), "l"(src));
}
__device__ __forceinline__ void cpa_commit() { asm volatile("cp.async.commit_group;" ::: "memory"); }
template<int N> __device__ __forceinline__ void cpa_wait() {
    asm volatile("cp.async.wait_group %0;" :: "n"(N) : "memory");
}
__device__ __forceinline__ void ldm_x4(uint32_t* r, uint32_t addr) {
    asm volatile("ldmatrix.sync.aligned.m8n8.x4.shared.b16 {%0,%1,%2,%3}, [%4];"
        : "=r"(r[0]), "=r"(r[1]), "=r"(r[2]), "=r"(r[3]) : "r"(addr));
}
__device__ __forceinline__ void mma_bf16(float* d, const uint32_t* a, const uint32_t* b) {
    asm volatile("mma.sync.aligned.m16n8k16.row.col.f32.bf16.bf16.f32 "
        "{%0,%1,%2,%3}, {%4,%5,%6,%7}, {%8,%9}, {%0,%1,%2,%3};"
        : "+f"(d[0]), "+f"(d[1]), "+f"(d[2]), "+f"(d[3])
        : "r"(a[0]), "r"(a[1]), "r"(a[2]), "r"(a[3]), "r"(b[0]), "r"(b[1]));
}

// ---------------- fp32 -> bf16 hi/lo split ----------------
__global__ void split_kernel(const float* __restrict__ s, bf16* __restrict__ h,
                             bf16* __restrict__ l, int n4) {
    int i = blockIdx.x * 256 + threadIdx.x;
    if (i >= n4) return;
    float4 v = reinterpret_cast<const float4*>(s)[i];
    bf16 h0 = __float2bfloat16(v.x), h1 = __float2bfloat16(v.y);
    bf16 h2 = __float2bfloat16(v.z), h3 = __float2bfloat16(v.w);
    __nv_bfloat162 hp0{h0, h1}, hp1{h2, h3};
    __nv_bfloat162 lp0{__float2bfloat16(v.x - __bfloat162float(h0)),
                       __float2bfloat16(v.y - __bfloat162float(h1))};
    __nv_bfloat162 lp1{__float2bfloat16(v.z - __bfloat162float(h2)),
                       __float2bfloat16(v.w - __bfloat162float(h3))};
    reinterpret_cast<__nv_bfloat162*>(h)[i * 2 + 0] = hp0;
    reinterpret_cast<__nv_bfloat162*>(h)[i * 2 + 1] = hp1;
    reinterpret_cast<__nv_bfloat162*>(l)[i * 2 + 0] = lp0;
    reinterpret_cast<__nv_bfloat162*>(l)[i * 2 + 1] = lp1;
}

// ---------------- HMMA split-bf16 GEMM (R5 loop, templated M-tile) ----------------
// C[b,p] = sum_k X[b,k]*Wm[p,k]  (both K-major). 3-product split: hh + hl + lh.
// MI = #16-row tiles per warp-column (4 -> CTA rows 128, 2 -> CTA rows 64).
// MODE 0: f = mu*acc -> outf+splits | 1: f = acc-aux -> splits | 2: f = aux-mu*acc -> outf
#define PITCH 80                         // 32 bf16 + 16B pad; conflict-free
#define WT_B (128 * PITCH)               // W tile bytes (always 128 rows)

template<int MODE, int MI>
__global__ __launch_bounds__(256, 2)
void mma_gemm(const bf16* __restrict__ Xh, const bf16* __restrict__ Xl,
              const bf16* __restrict__ Bh, const bf16* __restrict__ Bl,
              int K, int P,
              float* __restrict__ outf, bf16* __restrict__ outh, bf16* __restrict__ outl,
              const float* __restrict__ aux, const float* __restrict__ mu, int muidx)
{
    constexpr int TBR   = MI * 32;           // CTA rows
    constexpr int XT_B  = TBR * PITCH;       // one X tile bytes
    constexpr int STAGE = 2 * XT_B + 2 * WT_B;
    constexpr int XCH   = 8 * TBR;           // 16B chunks in both X tiles (TBR*4 each)
    constexpr int NLOAD = MI + 4;            // (XCH + 2048/2) / 256 chunks per thread

    extern __shared__ char smem[];
    const uint32_t sb = smem_u32(smem);
    const int tid = threadIdx.x, lane = tid & 31, wid = tid >> 5;
    const int wr = wid >> 2, wc = wid & 3;          // 2 x 4 warp grid
    const int b0 = blockIdx.x * TBR, p0 = blockIdx.y * 128;

    float acc[MI][4][4];
    #pragma unroll
    for (int i = 0; i < MI; i++)
        #pragma unroll
        for (int j = 0; j < 4; j++)
            #pragma unroll
            for (int q = 0; q < 4; q++) acc[i][j][q] = 0.f;

    const int nch = K >> 5;   // KC = 32

    auto load_stage = [&](int s, int c) {
        const int k0 = c * 32;
        const uint32_t st = sb + s * STAGE;
        const bf16* xs0 = Xh + (size_t)b0 * K + k0;
        const bf16* xs1 = Xl + (size_t)b0 * K + k0;
        const bf16* ws0 = Bh + (size_t)p0 * K + k0;
        const bf16* ws1 = Bl + (size_t)p0 * K + k0;
        #pragma unroll
        for (int l = 0; l < NLOAD; l++) {
            int id = tid + l * 256;
            if (id < XCH) {                          // X: 2 tiles, TBR rows x 4 chunks
                int t = id / (4 * TBR), r = id % (4 * TBR);
                int row = r >> 2, ch = r & 3;
                const bf16* g = t ? xs1 : xs0;
                cpa16(st + t * XT_B + row * PITCH + ch * 16,
                      g + (size_t)row * K + ch * 8);
            } else {                                 // W: 2 tiles, 128 rows x 4 chunks
                int id2 = id - XCH;
                int t = id2 >> 9, r = id2 & 511;
                int row = r >> 2, ch = r & 3;
                const bf16* g = t ? ws1 : ws0;
                cpa16(st + 2 * XT_B + t * WT_B + row * PITCH + ch * 16,
                      g + (size_t)row * K + ch * 8);
            }
        }
        cpa_commit();
    };

    load_stage(0, 0);
    if (nch > 1) load_stage(1, 1);

    for (int c = 0; c < nch; c++) {
        const int s = c & 1;
        if (c + 1 < nch) cpa_wait<1>(); else cpa_wait<0>();
        __syncthreads();

        const uint32_t xs = sb + s * STAGE;
        const uint32_t ws = xs + 2 * XT_B;
        #pragma unroll
        for (int ks = 0; ks < 2; ks++) {
            const int kb = ks * 32;
            uint32_t ah[MI][4], al[MI][4];
            #pragma unroll
            for (int mi = 0; mi < MI; mi++) {
                uint32_t a = xs + (uint32_t)(wr * (MI * 16) + mi * 16 + (lane & 15)) * PITCH
                           + kb + ((lane >> 4) << 4);
                ldm_x4(ah[mi], a);
                ldm_x4(al[mi], a + XT_B);
            }
            #pragma unroll
            for (int nb = 0; nb < 2; nb++) {
                uint32_t a = ws + (uint32_t)(wc * 32 + nb * 16 + ((lane >> 4) << 3)
                           + (lane & 7)) * PITCH
                           + kb + (((lane >> 3) & 1) << 4);
                uint32_t bh[4], bl[4];
                ldm_x4(bh, a);
                ldm_x4(bl, a + WT_B);
                #pragma unroll
                for (int mi = 0; mi < MI; mi++) {
                    mma_bf16(acc[mi][nb*2],   ah[mi], bh);
                    mma_bf16(acc[mi][nb*2+1], ah[mi], bh + 2);
                }
                #pragma unroll
                for (int mi = 0; mi < MI; mi++) {
                    mma_bf16(acc[mi][nb*2],   ah[mi], bl);
                    mma_bf16(acc[mi][nb*2+1], ah[mi], bl + 2);
                }
                #pragma unroll
                for (int mi = 0; mi < MI; mi++) {
                    mma_bf16(acc[mi][nb*2],   al[mi], bh);
                    mma_bf16(acc[mi][nb*2+1], al[mi], bh + 2);
                }
            }
        }
        __syncthreads();
        if (c + 2 < nch) load_stage(s, c + 2);
    }

    // ---------------- epilogue ----------------
    const float m = (MODE != 1) ? __ldg(mu + muidx) : 0.f;
    const int rbase = b0 + wr * (MI * 16) + (lane >> 2);
    const int cbase = p0 + wc * 32 + (lane & 3) * 2;

    #pragma unroll
    for (int mi = 0; mi < MI; mi++) {
        #pragma unroll
        for (int h = 0; h < 2; h++) {
            const int row = rbase + mi * 16 + h * 8;
            #pragma unroll
            for (int ni = 0; ni < 4; ni++) {
                const size_t off = (size_t)row * P + cbase + ni * 8;
                float v0 = acc[mi][ni][h * 2], v1 = acc[mi][ni][h * 2 + 1];
                if (MODE == 0) { v0 *= m; v1 *= m; }
                else {
                    float2 a2 = *reinterpret_cast<const float2*>(aux + off);
                    if (MODE == 1) { v0 -= a2.x; v1 -= a2.y; }
                    else { v0 = a2.x - m * v0; v1 = a2.y - m * v1; }
                }
                if (MODE == 0 || MODE == 2)
                    *reinterpret_cast<float2*>(outf + off) = make_float2(v0, v1);
                if (MODE == 0 || MODE == 1) {
                    bf16 h0 = __float2bfloat16(v0), h1 = __float2bfloat16(v1);
                    __nv_bfloat162 hp{h0, h1};
                    __nv_bfloat162 lp{__float2bfloat16(v0 - __bfloat162float(h0)),
                                      __float2bfloat16(v1 - __bfloat162float(h1))};
                    *reinterpret_cast<__nv_bfloat162*>(outh + off) = hp;
                    *reinterpret_cast<__nv_bfloat162*>(outl + off) = lp;
                }
            }
        }
    }
}

// ---------------- shrink: exact kth-largest via bitwise binary search ----------------
__global__ __launch_bounds__(256, 4)
void shrink2(float* __restrict__ x, bf16* __restrict__ xh, bf16* __restrict__ xl,
             const float* __restrict__ beta, int bidx, int kth)
{
    __shared__ int wsum[2][8];
    const int tid = threadIdx.x, wid = tid >> 5, lane = tid & 31;
    float* row = x + (size_t)blockIdx.x * NDIM;
    const int e0 = tid * 8;

    float e[8];
    float4 a = *reinterpret_cast<const float4*>(row + e0);
    float4 b4 = *reinterpret_cast<const float4*>(row + e0 + 4);
    e[0]=a.x; e[1]=a.y; e[2]=a.z; e[3]=a.w; e[4]=b4.x; e[5]=b4.y; e[6]=b4.z; e[7]=b4.w;
    uint32_t k[8];
    #pragma unroll
    for (int i = 0; i < 8; i++) k[i] = __float_as_uint(fabsf(e[i]));

    uint32_t thr = 0;
    for (int bit = 30; bit >= 0; bit--) {
        uint32_t cand = thr | (1u << bit);
        int c = 0;
        #pragma unroll
        for (int i = 0; i < 8; i++) c += (k[i] >= cand);
        c = __reduce_add_sync(0xFFFFFFFFu, c);
        const int buf = bit & 1;
        if (lane == 0) wsum[buf][wid] = c;
        __syncthreads();
        int tot = wsum[buf][0]+wsum[buf][1]+wsum[buf][2]+wsum[buf][3]
                + wsum[buf][4]+wsum[buf][5]+wsum[buf][6]+wsum[buf][7];
        if (tot >= kth) thr = cand;
    }

    const float thf = __uint_as_float(thr);
    const float b = beta[bidx];
    float r[8];
    #pragma unroll
    for (int i = 0; i < 8; i++) {
        float val = e[i];
        float u = val / b;
        float soft = b * copysignf(fmaxf(fabsf(u) - 1.0f, 0.0f), u);
        r[i] = (fabsf(val) >= thf) ? val : soft;
    }
    *reinterpret_cast<float4*>(row + e0)     = make_float4(r[0], r[1], r[2], r[3]);
    *reinterpret_cast<float4*>(row + e0 + 4) = make_float4(r[4], r[5], r[6], r[7]);

    const size_t go = (size_t)blockIdx.x * NDIM + e0;
    #pragma unroll
    for (int i = 0; i < 8; i += 2) {
        bf16 h0 = __float2bfloat16(r[i]), h1 = __float2bfloat16(r[i+1]);
        __nv_bfloat162 hp{h0, h1};
        __nv_bfloat162 lp{__float2bfloat16(r[i]   - __bfloat162float(h0)),
                          __float2bfloat16(r[i+1] - __bfloat162float(h1))};
        *reinterpret_cast<__nv_bfloat162*>(xh + go + i) = hp;
        *reinterpret_cast<__nv_bfloat162*>(xl + go + i) = lp;
    }
}

// ---------------------------------------------------------------------------
extern "C" void kernel_launch(void* const* d_in, const int* in_sizes, int n_in,
                              void* d_out, int out_size)
{
    const float* y    = (const float*)d_in[0];   // [8192, 512]
    const float* A    = (const float*)d_in[1];   // [512, 2048]
    const float* W    = (const float*)d_in[2];   // [2048, 512] = A^T
    const float* beta = (const float*)d_in[3];
    const float* mu   = (const float*)d_in[4];
    float* x = (float*)d_out;                    // [8192, 2048]

    constexpr int SMEM_128 = 2 * (2 * 128 * PITCH + 2 * WT_B);   // 81920
    constexpr int SMEM_64  = 2 * (2 * 64  * PITCH + 2 * WT_B);   // 61440

    cudaFuncSetAttribute(mma_gemm<0,4>, cudaFuncAttributeMaxDynamicSharedMemorySize, SMEM_128);
    cudaFuncSetAttribute(mma_gemm<1,2>, cudaFuncAttributeMaxDynamicSharedMemorySize, SMEM_64);
    cudaFuncSetAttribute(mma_gemm<2,4>, cudaFuncAttributeMaxDynamicSharedMemorySize, SMEM_128);

    bf16 *xh, *xl, *rh, *rl, *yh, *yl, *Ahp, *Alp, *Wh, *Wl;
    { void* p; cudaGetSymbolAddress(&p, g_xh); xh = (bf16*)p; }
    { void* p; cudaGetSymbolAddress(&p, g_xl); xl = (bf16*)p; }
    { void* p; cudaGetSymbolAddress(&p, g_rh); rh = (bf16*)p; }
    { void* p; cudaGetSymbolAddress(&p, g_rl); rl = (bf16*)p; }
    { void* p; cudaGetSymbolAddress(&p, g_yh); yh = (bf16*)p; }
    { void* p; cudaGetSymbolAddress(&p, g_yl); yl = (bf16*)p; }
    { void* p; cudaGetSymbolAddress(&p, g_Ah); Ahp = (bf16*)p; }
    { void* p; cudaGetSymbolAddress(&p, g_Al); Alp = (bf16*)p; }
    { void* p; cudaGetSymbolAddress(&p, g_Wh); Wh = (bf16*)p; }
    { void* p; cudaGetSymbolAddress(&p, g_Wl); Wl = (bf16*)p; }

    // splits of inputs
    {
        int n4 = BATCH * MDIM / 4;
        split_kernel<<<(n4 + 255) / 256, 256>>>(y, yh, yl, n4);
        n4 = MDIM * NDIM / 4;
        split_kernel<<<(n4 + 255) / 256, 256>>>(A, Ahp, Alp, n4);
        split_kernel<<<(n4 + 255) / 256, 256>>>(W, Wh, Wl, n4);
    }

    const dim3 blk(256);
    const dim3 gN(BATCH / 128, NDIM / 128);   // (64, 16)  1024 CTAs
    const dim3 gM(BATCH / 64,  MDIM / 128);   // (128, 4)  512 CTAs
    const int kth[6] = {0, 24, 49, 73, 98, 122};

    // x0 = mu0 * (y @ A):  X = y (K=512), B = W rows ([N,K]), P=2048
    mma_gemm<0,4><<<gN, blk, SMEM_128>>>(yh, yl, Wh, Wl, MDIM, NDIM,
                                         x, xh, xl, nullptr, mu, 0);

    for (int t = 1; t <= 5; t++) {
        // r = x @ A.T - y:  X = x (K=2048), B = A rows, P=512 -- 64-row tiles
        mma_gemm<1,2><<<gM, blk, SMEM_64>>>(xh, xl, Ahp, Alp, NDIM, MDIM,
                                            nullptr, rh, rl, y, mu, t);
        // v = x - mu*(r @ W.T):  X = r (K=512), B = W rows, P=2048 (in-place on x)
        mma_gemm<2,4><<<gN, blk, SMEM_128>>>(rh, rl, Wh, Wl, MDIM, NDIM,
                                             x, nullptr, nullptr, x, mu, t);
        // x = shrink(v)
        shrink2<<<BATCH, blk>>>(x, xh, xl, beta, t, kth[t]);
    }
}

// round 10
// speedup vs baseline: 1.0535x; 1.0298x over previous
#include <cuda_runtime.h>
#include <cuda_bf16.h>
#include <cstdint>

#define BATCH 8192
#define MDIM  512
#define NDIM  2048

typedef __nv_bfloat16 bf16;

// ---------------- static device scratch (no allocs allowed) ----------------
__device__ __align__(256) bf16 g_xh[(size_t)BATCH * NDIM];
__device__ __align__(256) bf16 g_xl[(size_t)BATCH * NDIM];
__device__ __align__(256) bf16 g_rh[(size_t)BATCH * MDIM];
__device__ __align__(256) bf16 g_rl[(size_t)BATCH * MDIM];
__device__ __align__(256) bf16 g_yh[(size_t)BATCH * MDIM];
__device__ __align__(256) bf16 g_yl[(size_t)BATCH * MDIM];
__device__ __align__(256) bf16 g_Ah[(size_t)MDIM * NDIM];
__device__ __align__(256) bf16 g_Al[(size_t)MDIM * NDIM];
__device__ __align__(256) bf16 g_Wh[(size_t)NDIM * MDIM];
__device__ __align__(256) bf16 g_Wl[(size_t)NDIM * MDIM];
__device__ __align__(256) float g_part[2][(size_t)BATCH * MDIM];   // split-K partials

// ---------------- PTX helpers (base-ISA only) ----------------
__device__ __forceinline__ uint32_t smem_u32(const void* p) {
    uint32_t a;
    asm("{ .reg .u64 t; cvta.to.shared.u64 t, %1; cvt.u32.u64 %0, t; }" : "=r"(a) : "l"(p));
    return a;
}
__device__ __forceinline__ void cpa16(uint32_t dst, const void* src) {
    asm volatile("cp.async.cg.shared.global [%0], [%1], 16;" :: "r"(dst), "l"(src));
}
__device__ __forceinline__ void cpa_commit() { asm volatile("cp.async.commit_group;" ::: "memory"); }
template<int N> __device__ __forceinline__ void cpa_wait() {
    asm volatile("cp.async.wait_group %0;" :: "n"(N) : "memory");
}
__device__ __forceinline__ void ldm_x4(uint32_t* r, uint32_t addr) {
    asm volatile("ldmatrix.sync.aligned.m8n8.x4.shared.b16 {%0,%1,%2,%3}, [%4];"
        : "=r"(r[0]), "=r"(r[1]), "=r"(r[2]), "=r"(r[3]) : "r"(addr));
}
__device__ __forceinline__ void mma_bf16(float* d, const uint32_t* a, const uint32_t* b) {
    asm volatile("mma.sync.aligned.m16n8k16.row.col.f32.bf16.bf16.f32 "
        "{%0,%1,%2,%3}, {%4,%5,%6,%7}, {%8,%9}, {%0,%1,%2,%3};"
        : "+f"(d[0]), "+f"(d[1]), "+f"(d[2]), "+f"(d[3])
        : "r"(a[0]), "r"(a[1]), "r"(a[2]), "r"(a[3]), "r"(b[0]), "r"(b[1]));
}

__device__ __forceinline__ void split2(float v0, float v1, bf16* h, bf16* l) {
    bf16 h0 = __float2bfloat16(v0), h1 = __float2bfloat16(v1);
    __nv_bfloat162 hp{h0, h1};
    __nv_bfloat162 lp{__float2bfloat16(v0 - __bfloat162float(h0)),
                      __float2bfloat16(v1 - __bfloat162float(h1))};
    *reinterpret_cast<__nv_bfloat162*>(h) = hp;
    *reinterpret_cast<__nv_bfloat162*>(l) = lp;
}

// ---------------- fp32 -> bf16 hi/lo split ----------------
__global__ void split_kernel(const float* __restrict__ s, bf16* __restrict__ h,
                             bf16* __restrict__ l, int n4) {
    int i = blockIdx.x * 256 + threadIdx.x;
    if (i >= n4) return;
    float4 v = reinterpret_cast<const float4*>(s)[i];
    split2(v.x, v.y, h + i * 4, l + i * 4);
    split2(v.z, v.w, h + i * 4 + 2, l + i * 4 + 2);
}

// ---------------- combine split-K partials: r = p0 + p1 - y -> splits ----------------
__global__ void combine_r(const float* __restrict__ p0, const float* __restrict__ p1,
                          const float* __restrict__ y, bf16* __restrict__ rh,
                          bf16* __restrict__ rl, int n4) {
    int i = blockIdx.x * 256 + threadIdx.x;
    if (i >= n4) return;
    float4 a = reinterpret_cast<const float4*>(p0)[i];
    float4 b = reinterpret_cast<const float4*>(p1)[i];
    float4 c = reinterpret_cast<const float4*>(y)[i];
    float v0 = a.x + b.x - c.x, v1 = a.y + b.y - c.y;
    float v2 = a.z + b.z - c.z, v3 = a.w + b.w - c.w;
    split2(v0, v1, rh + i * 4, rl + i * 4);
    split2(v2, v3, rh + i * 4 + 2, rl + i * 4 + 2);
}

// ---------------- HMMA split-bf16 GEMM ----------------
// C[b,p] = sum_k X[b,k]*Wm[p,k]  (both K-major). 3-product split: hh + hl + lh.
// MODE 0: f = mu*acc -> outf+splits | 2: f = aux-mu*acc -> outf
// MODE 3: split-K partial, f = acc -> outf[blockIdx.z * BATCH*MDIM + ...]
#define PITCH 80
#define WT_B (128 * PITCH)

template<int MODE>
__global__ __launch_bounds__(256, 2)
void mma_gemm(const bf16* __restrict__ Xh, const bf16* __restrict__ Xl,
              const bf16* __restrict__ Bh, const bf16* __restrict__ Bl,
              int K, int P,
              float* __restrict__ outf, bf16* __restrict__ outh, bf16* __restrict__ outl,
              const float* __restrict__ aux, const float* __restrict__ mu, int muidx)
{
    constexpr int XT_B  = 128 * PITCH;
    constexpr int STAGE = 2 * XT_B + 2 * WT_B;

    extern __shared__ char smem[];
    const uint32_t sb = smem_u32(smem);
    const int tid = threadIdx.x, lane = tid & 31, wid = tid >> 5;
    const int wr = wid >> 2, wc = wid & 3;
    const int b0 = blockIdx.x * 128, p0 = blockIdx.y * 128;
    const int koff = (MODE == 3) ? (int)blockIdx.z * (K >> 1) : 0;
    const int nch  = ((MODE == 3) ? (K >> 1) : K) >> 5;

    float acc[4][4][4];
    #pragma unroll
    for (int i = 0; i < 4; i++)
        #pragma unroll
        for (int j = 0; j < 4; j++)
            #pragma unroll
            for (int q = 0; q < 4; q++) acc[i][j][q] = 0.f;

    auto load_stage = [&](int s, int c) {
        const int k0 = koff + c * 32;
        const uint32_t st = sb + s * STAGE;
        const bf16* xs0 = Xh + (size_t)b0 * K + k0;
        const bf16* xs1 = Xl + (size_t)b0 * K + k0;
        const bf16* ws0 = Bh + (size_t)p0 * K + k0;
        const bf16* ws1 = Bl + (size_t)p0 * K + k0;
        #pragma unroll
        for (int l = 0; l < 8; l++) {
            int id = tid + l * 256;
            if (id < 1024) {                         // X: 2 tiles, 128 rows x 4 chunks
                int t = id >> 9, r = id & 511;
                int row = r >> 2, ch = r & 3;
                const bf16* g = t ? xs1 : xs0;
                cpa16(st + t * XT_B + row * PITCH + ch * 16,
                      g + (size_t)row * K + ch * 8);
            } else {                                 // W: 2 tiles, 128 rows x 4 chunks
                int id2 = id - 1024;
                int t = id2 >> 9, r = id2 & 511;
                int row = r >> 2, ch = r & 3;
                const bf16* g = t ? ws1 : ws0;
                cpa16(st + 2 * XT_B + t * WT_B + row * PITCH + ch * 16,
                      g + (size_t)row * K + ch * 8);
            }
        }
        cpa_commit();
    };

    load_stage(0, 0);
    if (nch > 1) load_stage(1, 1);

    for (int c = 0; c < nch; c++) {
        const int s = c & 1;
        if (c + 1 < nch) cpa_wait<1>(); else cpa_wait<0>();
        __syncthreads();

        const uint32_t xs = sb + s * STAGE;
        const uint32_t ws = xs + 2 * XT_B;
        #pragma unroll
        for (int ks = 0; ks < 2; ks++) {
            const int kb = ks * 32;
            uint32_t ah[4][4], al[4][4];
            #pragma unroll
            for (int mi = 0; mi < 4; mi++) {
                uint32_t a = xs + (uint32_t)(wr * 64 + mi * 16 + (lane & 15)) * PITCH
                           + kb + ((lane >> 4) << 4);
                ldm_x4(ah[mi], a);
                ldm_x4(al[mi], a + XT_B);
            }
            #pragma unroll
            for (int nb = 0; nb < 2; nb++) {
                uint32_t a = ws + (uint32_t)(wc * 32 + nb * 16 + ((lane >> 4) << 3)
                           + (lane & 7)) * PITCH
                           + kb + (((lane >> 3) & 1) << 4);
                uint32_t bh[4], bl[4];
                ldm_x4(bh, a);
                ldm_x4(bl, a + WT_B);
                #pragma unroll
                for (int mi = 0; mi < 4; mi++) {
                    mma_bf16(acc[mi][nb*2],   ah[mi], bh);
                    mma_bf16(acc[mi][nb*2+1], ah[mi], bh + 2);
                }
                #pragma unroll
                for (int mi = 0; mi < 4; mi++) {
                    mma_bf16(acc[mi][nb*2],   ah[mi], bl);
                    mma_bf16(acc[mi][nb*2+1], ah[mi], bl + 2);
                }
                #pragma unroll
                for (int mi = 0; mi < 4; mi++) {
                    mma_bf16(acc[mi][nb*2],   al[mi], bh);
                    mma_bf16(acc[mi][nb*2+1], al[mi], bh + 2);
                }
            }
        }
        __syncthreads();
        if (c + 2 < nch) load_stage(s, c + 2);
    }

    // ---------------- epilogue ----------------
    const float m = (MODE == 0 || MODE == 2) ? __ldg(mu + muidx) : 0.f;
    float* op = outf;
    if (MODE == 3) op = outf + (size_t)blockIdx.z * BATCH * MDIM;
    const int rbase = b0 + wr * 64 + (lane >> 2);
    const int cbase = p0 + wc * 32 + (lane & 3) * 2;

    #pragma unroll
    for (int mi = 0; mi < 4; mi++) {
        #pragma unroll
        for (int h = 0; h < 2; h++) {
            const int row = rbase + mi * 16 + h * 8;
            #pragma unroll
            for (int ni = 0; ni < 4; ni++) {
                const size_t off = (size_t)row * P + cbase + ni * 8;
                float v0 = acc[mi][ni][h * 2], v1 = acc[mi][ni][h * 2 + 1];
                if (MODE == 0) { v0 *= m; v1 *= m; }
                else if (MODE == 2) {
                    float2 a2 = *reinterpret_cast<const float2*>(aux + off);
                    v0 = a2.x - m * v0; v1 = a2.y - m * v1;
                }
                *reinterpret_cast<float2*>(op + off) = make_float2(v0, v1);
                if (MODE == 0)
                    split2(v0, v1, outh + off, outl + off);
            }
        }
    }
}

// ---------------- shrink: exact kth-largest via bitwise binary search ----------------
__global__ __launch_bounds__(256, 4)
void shrink2(float* __restrict__ x, bf16* __restrict__ xh, bf16* __restrict__ xl,
             const float* __restrict__ beta, int bidx, int kth)
{
    __shared__ int wsum[2][8];
    const int tid = threadIdx.x, wid = tid >> 5, lane = tid & 31;
    float* row = x + (size_t)blockIdx.x * NDIM;
    const int e0 = tid * 8;

    float e[8];
    float4 a = *reinterpret_cast<const float4*>(row + e0);
    float4 b4 = *reinterpret_cast<const float4*>(row + e0 + 4);
    e[0]=a.x; e[1]=a.y; e[2]=a.z; e[3]=a.w; e[4]=b4.x; e[5]=b4.y; e[6]=b4.z; e[7]=b4.w;
    uint32_t k[8];
    #pragma unroll
    for (int i = 0; i < 8; i++) k[i] = __float_as_uint(fabsf(e[i]));

    uint32_t thr = 0;
    for (int bit = 30; bit >= 0; bit--) {
        uint32_t cand = thr | (1u << bit);
        int c = 0;
        #pragma unroll
        for (int i = 0; i < 8; i++) c += (k[i] >= cand);
        c = __reduce_add_sync(0xFFFFFFFFu, c);
        const int buf = bit & 1;
        if (lane == 0) wsum[buf][wid] = c;
        __syncthreads();
        int tot = wsum[buf][0]+wsum[buf][1]+wsum[buf][2]+wsum[buf][3]
                + wsum[buf][4]+wsum[buf][5]+wsum[buf][6]+wsum[buf][7];
        if (tot >= kth) thr = cand;
    }

    const float thf = __uint_as_float(thr);
    const float b = beta[bidx];
    float r[8];
    #pragma unroll
    for (int i = 0; i < 8; i++) {
        float val = e[i];
        float u = val / b;
        float soft = b * copysignf(fmaxf(fabsf(u) - 1.0f, 0.0f), u);
        r[i] = (fabsf(val) >= thf) ? val : soft;
    }
    *reinterpret_cast<float4*>(row + e0)     = make_float4(r[0], r[1], r[2], r[3]);
    *reinterpret_cast<float4*>(row + e0 + 4) = make_float4(r[4], r[5], r[6], r[7]);

    const size_t go = (size_t)blockIdx.x * NDIM + e0;
    #pragma unroll
    for (int i = 0; i < 8; i += 2)
        split2(r[i], r[i+1], xh + go + i, xl + go + i);
}

// ---------------------------------------------------------------------------
extern "C" void kernel_launch(void* const* d_in, const int* in_sizes, int n_in,
                              void* d_out, int out_size)
{
    const float* y    = (const float*)d_in[0];   // [8192, 512]
    const float* A    = (const float*)d_in[1];   // [512, 2048]
    const float* W    = (const float*)d_in[2];   // [2048, 512] = A^T
    const float* beta = (const float*)d_in[3];
    const float* mu   = (const float*)d_in[4];
    float* x = (float*)d_out;                    // [8192, 2048]

    constexpr int SMEM_128 = 2 * (2 * 128 * PITCH + 2 * WT_B);   // 81920

    cudaFuncSetAttribute(mma_gemm<0>, cudaFuncAttributeMaxDynamicSharedMemorySize, SMEM_128);
    cudaFuncSetAttribute(mma_gemm<2>, cudaFuncAttributeMaxDynamicSharedMemorySize, SMEM_128);
    cudaFuncSetAttribute(mma_gemm<3>, cudaFuncAttributeMaxDynamicSharedMemorySize, SMEM_128);

    bf16 *xh, *xl, *rh, *rl, *yh, *yl, *Ahp, *Alp, *Wh, *Wl;
    float *part;
    { void* p; cudaGetSymbolAddress(&p, g_xh); xh = (bf16*)p; }
    { void* p; cudaGetSymbolAddress(&p, g_xl); xl = (bf16*)p; }
    { void* p; cudaGetSymbolAddress(&p, g_rh); rh = (bf16*)p; }
    { void* p; cudaGetSymbolAddress(&p, g_rl); rl = (bf16*)p; }
    { void* p; cudaGetSymbolAddress(&p, g_yh); yh = (bf16*)p; }
    { void* p; cudaGetSymbolAddress(&p, g_yl); yl = (bf16*)p; }
    { void* p; cudaGetSymbolAddress(&p, g_Ah); Ahp = (bf16*)p; }
    { void* p; cudaGetSymbolAddress(&p, g_Al); Alp = (bf16*)p; }
    { void* p; cudaGetSymbolAddress(&p, g_Wh); Wh = (bf16*)p; }
    { void* p; cudaGetSymbolAddress(&p, g_Wl); Wl = (bf16*)p; }
    { void* p; cudaGetSymbolAddress(&p, g_part); part = (float*)p; }

    // splits of inputs
    {
        int n4 = BATCH * MDIM / 4;
        split_kernel<<<(n4 + 255) / 256, 256>>>(y, yh, yl, n4);
        n4 = MDIM * NDIM / 4;
        split_kernel<<<(n4 + 255) / 256, 256>>>(A, Ahp, Alp, n4);
        split_kernel<<<(n4 + 255) / 256, 256>>>(W, Wh, Wl, n4);
    }

    const dim3 blk(256);
    const dim3 gN(BATCH / 128, NDIM / 128);       // (64, 16)  1024 CTAs
    const dim3 gM(BATCH / 128, MDIM / 128, 2);    // (64, 4, 2) 512 CTAs split-K
    const int kth[6] = {0, 24, 49, 73, 98, 122};
    const int nr4 = BATCH * MDIM / 4;

    // x0 = mu0 * (y @ A):  X = y (K=512), B = W rows ([N,K]), P=2048
    mma_gemm<0><<<gN, blk, SMEM_128>>>(yh, yl, Wh, Wl, MDIM, NDIM,
                                       x, xh, xl, nullptr, mu, 0);

    for (int t = 1; t <= 5; t++) {
        // split-K partials of x @ A.T:  X = x (K=2048 halves), B = A rows, P=512
        mma_gemm<3><<<gM, blk, SMEM_128>>>(xh, xl, Ahp, Alp, NDIM, MDIM,
                                           part, nullptr, nullptr, nullptr, mu, t);
        // r = p0 + p1 - y  -> rh/rl splits
        combine_r<<<(nr4 + 255) / 256, blk>>>(part, part + (size_t)BATCH * MDIM, y,
                                              rh, rl, nr4);
        // v = x - mu*(r @ W.T):  X = r (K=512), B = W rows, P=2048 (in-place on x)
        mma_gemm<2><<<gN, blk, SMEM_128>>>(rh, rl, Wh, Wl, MDIM, NDIM,
                                           x, nullptr, nullptr, x, mu, t);
        // x = shrink(v)
        shrink2<<<BATCH, blk>>>(x, xh, xl, beta, t, kth[t]);
    }
}